// round 8
// baseline (speedup 1.0000x reference)
#include <cuda_runtime.h>

#define N_NODES 50000
#define N_EDGES 800000

// Scratch (no allocations allowed). Layout: g_q[node*64 + d*8 + h] (transposed
// within the row so each (edge,d) gather is 32 contiguous bytes).
__device__ float g_q[N_NODES * 64];
__device__ float g_k[N_NODES * 64];
__device__ float g_segsum[N_NODES * 8];

typedef unsigned long long u64;

__device__ __forceinline__ u64 pk2(float a, float b) {
    u64 r; asm("mov.b64 %0, {%1, %2};" : "=l"(r) : "f"(a), "f"(b)); return r;
}
__device__ __forceinline__ void fma2(u64 &d, u64 a, u64 b) {
    asm("fma.rn.f32x2 %0, %1, %2, %0;" : "+l"(d) : "l"(a), "l"(b));
}
__device__ __forceinline__ void unpk2(u64 a, float &x, float &y) {
    asm("mov.b64 {%0, %1}, %2;" : "=f"(x), "=f"(y) : "l"(a));
}

// Fused QKV projection with packed f32x2 FMA. Dynamic smem:
//   [0)      sW[3][4096]   weights
//   [12288)  sb[3][64]     biases
//   [12480)  sxT[64][34]   x tile transposed (padded)
// Tile: 32 rows. Thread (g,col): rows 8g..8g+7 as 4 row-pairs, column col.
// q,k are written with the in-row transpose perm: out column = (col%8)*8 + col/8.
extern __shared__ float dsm[];
__global__ void qkv_kernel(const float* __restrict__ x,
                           const float* __restrict__ Wq, const float* __restrict__ bq,
                           const float* __restrict__ Wk, const float* __restrict__ bk,
                           const float* __restrict__ Wv, const float* __restrict__ bv,
                           float* __restrict__ vout) {
    float* sW  = dsm;             // 3*4096
    float* sb  = dsm + 12288;     // 3*64
    float* sxT = dsm + 12480;     // 64*34

    int tid = threadIdx.x;
    for (int i = tid; i < 4096; i += 256) {
        sW[i]        = Wq[i];
        sW[4096 + i] = Wk[i];
        sW[8192 + i] = Wv[i];
    }
    if (tid < 64) {
        sb[tid]       = bq[tid];
        sb[64 + tid]  = bk[tid];
        sb[128 + tid] = bv[tid];
    }

    int col = tid & 63;
    int g   = tid >> 6;      // 0..3
    int r0t = g * 8;         // local row base
    int pcol = (col & 7) * 8 + (col >> 3);  // transposed column for q,k

    const int n_tiles = (N_NODES + 31) / 32;  // 1563
    for (int tile = blockIdx.x; tile < n_tiles; tile += gridDim.x) {
        int row0 = tile * 32;
        __syncthreads();
        for (int i = tid; i < 32 * 64; i += 256) {
            int r = i >> 6, c = i & 63;
            sxT[c * 34 + r] = (row0 + r < N_NODES) ? x[(row0 + r) * 64 + c] : 0.0f;
        }
        __syncthreads();

        u64 aq[4] = {0,0,0,0}, ak[4] = {0,0,0,0}, av[4] = {0,0,0,0};
        #pragma unroll 8
        for (int kk = 0; kk < 64; kk++) {
            float wqs = sW[kk * 64 + col];
            float wks = sW[4096 + kk * 64 + col];
            float wvs = sW[8192 + kk * 64 + col];
            u64 wq2 = pk2(wqs, wqs);
            u64 wk2 = pk2(wks, wks);
            u64 wv2 = pk2(wvs, wvs);
            const u64* xp = (const u64*)&sxT[kk * 34 + r0t];
            #pragma unroll
            for (int j = 0; j < 4; j++) {
                u64 xj = xp[j];
                fma2(aq[j], xj, wq2);
                fma2(ak[j], xj, wk2);
                fma2(av[j], xj, wv2);
            }
        }
        float bqv = sb[col], bkv = sb[64 + col], bvv = sb[128 + col];
        #pragma unroll
        for (int j = 0; j < 4; j++) {
            float q0, q1, k0, k1, v0, v1;
            unpk2(aq[j], q0, q1);
            unpk2(ak[j], k0, k1);
            unpk2(av[j], v0, v1);
            int row = row0 + r0t + 2 * j;
            if (row < N_NODES) {
                g_q[row * 64 + pcol]  = q0 + bqv;
                g_k[row * 64 + pcol]  = k0 + bkv;
                vout[row * 64 + col]  = v0 + bvv;
            }
            if (row + 1 < N_NODES) {
                g_q[(row + 1) * 64 + pcol] = q1 + bqv;
                g_k[(row + 1) * 64 + pcol] = k1 + bkv;
                vout[(row + 1) * 64 + col] = v1 + bvv;
            }
        }
    }
}

// Fused: prods + exp + segment-sum. Thread = (edge, d). With the transposed
// q/k layout, each thread's gather is 2x float4 from q and 2x float4 from k.
// Writes only prods (att is produced by norm_kernel from prods).
__global__ void prods_exp_kernel(const int* __restrict__ edge,
                                 float* __restrict__ prods_out) {
    int idx = blockIdx.x * blockDim.x + threadIdx.x;
    if (idx >= N_EDGES * 8) return;
    int e = idx >> 3;
    int d = idx & 7;
    int s = __ldg(&edge[e]);
    int t = __ldg(&edge[N_EDGES + e]);
    const float4* qr = (const float4*)(g_q + s * 64 + d * 8);
    const float4* kr = (const float4*)(g_k + t * 64 + d * 8);
    float4 q0 = qr[0], q1 = qr[1];
    float4 k0 = kr[0], k1 = kr[1];
    float acc = q0.x * k0.x + q0.y * k0.y + q0.z * k0.z + q0.w * k0.w
              + q1.x * k1.x + q1.y * k1.y + q1.z * k1.z + q1.w * k1.w;
    float p = acc * 0.35355339059327373f;  // 1/sqrt(8)
    prods_out[idx] = p;
    float ex = __expf(p);  // no max subtraction: p ~ N(0,1), cannot overflow
    atomicAdd(&g_segsum[t * 8 + d], ex);
}

// One edge per thread: att = exp(prods) / (segsum + 1e-16). MUFU exp/rcp are
// ~200K warp-instructions chip-wide (~1.5us), hidden under the memory stream.
__global__ void norm_kernel(const int* __restrict__ edge,
                            const float* __restrict__ prods,
                            float* __restrict__ att) {
    int e = blockIdx.x * blockDim.x + threadIdx.x;
    if (e >= N_EDGES) return;
    int t = __ldg(&edge[N_EDGES + e]);
    const float4* sp = (const float4*)&g_segsum[t * 8];
    float4 s0 = sp[0], s1 = sp[1];
    const float4* pp = (const float4*)&prods[(size_t)e * 8];
    float4 p0 = pp[0], p1 = pp[1];
    float4 a0, a1;
    a0.x = __expf(p0.x) * __frcp_rn(s0.x + 1e-16f);
    a0.y = __expf(p0.y) * __frcp_rn(s0.y + 1e-16f);
    a0.z = __expf(p0.z) * __frcp_rn(s0.z + 1e-16f);
    a0.w = __expf(p0.w) * __frcp_rn(s0.w + 1e-16f);
    a1.x = __expf(p1.x) * __frcp_rn(s1.x + 1e-16f);
    a1.y = __expf(p1.y) * __frcp_rn(s1.y + 1e-16f);
    a1.z = __expf(p1.z) * __frcp_rn(s1.z + 1e-16f);
    a1.w = __expf(p1.w) * __frcp_rn(s1.w + 1e-16f);
    float4* ap = (float4*)&att[(size_t)e * 8];
    ap[0] = a0;
    ap[1] = a1;
}

extern "C" void kernel_launch(void* const* d_in, const int* in_sizes, int n_in,
                              void* d_out, int out_size) {
    const float* x    = (const float*)d_in[0];
    const float* Wq   = (const float*)d_in[1];
    const float* bq   = (const float*)d_in[2];
    const float* Wk   = (const float*)d_in[3];
    const float* bk   = (const float*)d_in[4];
    const float* Wv   = (const float*)d_in[5];
    const float* bv   = (const float*)d_in[6];
    const int*   edge = (const int*)d_in[7];

    float* out   = (float*)d_out;
    float* att   = out;                                               // [E*8]
    float* vout  = out + (size_t)N_EDGES * 8;                         // [N*64]
    float* prods = out + (size_t)N_EDGES * 8 + (size_t)N_NODES * 64;  // [E*8]

    const int QKV_SMEM = (12288 + 192 + 64 * 34) * 4;  // 58624 bytes
    static void* segsum_ptr = nullptr;
    if (!segsum_ptr) {
        cudaFuncSetAttribute(qkv_kernel, cudaFuncAttributeMaxDynamicSharedMemorySize, QKV_SMEM);
        cudaGetSymbolAddress(&segsum_ptr, g_segsum);
    }

    // Zero segment sums via async memset (graph-capturable node, no kernel launch)
    cudaMemsetAsync(segsum_ptr, 0, N_NODES * 8 * sizeof(float), 0);

    qkv_kernel<<<592, 256, QKV_SMEM>>>(x, Wq, bq, Wk, bk, Wv, bv, vout);

    int n_ed = N_EDGES * 8;
    prods_exp_kernel<<<(n_ed + 255) / 256, 256>>>(edge, prods);
    norm_kernel<<<(N_EDGES + 255) / 256, 256>>>(edge, prods, att);
}

// round 9
// speedup vs baseline: 1.1327x; 1.1327x over previous
#include <cuda_runtime.h>
#include <cuda_fp16.h>

#define N_NODES 50000
#define N_EDGES 800000

// Scratch. q,k stored as fp16 in transposed-row layout: g_qh[node*64 + d*8 + h]
// so each (edge,d) gather is 16 contiguous bytes.
__device__ __half g_qh[N_NODES * 64];
__device__ __half g_kh[N_NODES * 64];
__device__ float  g_segsum[N_NODES * 8];

typedef unsigned long long u64;

__device__ __forceinline__ u64 pk2(float a, float b) {
    u64 r; asm("mov.b64 %0, {%1, %2};" : "=l"(r) : "f"(a), "f"(b)); return r;
}
__device__ __forceinline__ void fma2(u64 &d, u64 a, u64 b) {
    asm("fma.rn.f32x2 %0, %1, %2, %0;" : "+l"(d) : "l"(a), "l"(b));
}
__device__ __forceinline__ void unpk2(u64 a, float &x, float &y) {
    asm("mov.b64 {%0, %1}, %2;" : "=f"(x), "=f"(y) : "l"(a));
}

// Fused QKV projection with packed f32x2 FMA. Dynamic smem (57856 B, fits
// 4 CTAs/SM within the 227KB carveout):
//   [0)      sW[3][4096]   weights
//   [12288)  sxT[64][34]   x tile transposed (stride 34 keeps LDS.64 aligned)
// Tile: 32 rows. Thread (g,col): rows 8g..8g+7 as 4 row-pairs, column col.
// q,k written fp16 with in-row transpose perm: out column = (col%8)*8 + col/8.
extern __shared__ float dsm[];
__global__ void qkv_kernel(const float* __restrict__ x,
                           const float* __restrict__ Wq, const float* __restrict__ bq,
                           const float* __restrict__ Wk, const float* __restrict__ bk,
                           const float* __restrict__ Wv, const float* __restrict__ bv,
                           float* __restrict__ vout) {
    float* sW  = dsm;             // 3*4096
    float* sxT = dsm + 12288;     // 64*34

    int tid = threadIdx.x;
    for (int i = tid; i < 4096; i += 256) {
        sW[i]        = Wq[i];
        sW[4096 + i] = Wk[i];
        sW[8192 + i] = Wv[i];
    }

    int col = tid & 63;
    int g   = tid >> 6;      // 0..3
    int r0t = g * 8;         // local row base
    int pcol = (col & 7) * 8 + (col >> 3);  // transposed column for q,k

    // biases in registers (uniform per column)
    float bqv = __ldg(&bq[col]);
    float bkv = __ldg(&bk[col]);
    float bvv = __ldg(&bv[col]);

    const int n_tiles = (N_NODES + 31) / 32;  // 1563
    for (int tile = blockIdx.x; tile < n_tiles; tile += gridDim.x) {
        int row0 = tile * 32;
        __syncthreads();
        for (int i = tid; i < 32 * 64; i += 256) {
            int r = i >> 6, c = i & 63;
            sxT[c * 34 + r] = (row0 + r < N_NODES) ? x[(row0 + r) * 64 + c] : 0.0f;
        }
        __syncthreads();

        u64 aq[4] = {0,0,0,0}, ak[4] = {0,0,0,0}, av[4] = {0,0,0,0};
        #pragma unroll 8
        for (int kk = 0; kk < 64; kk++) {
            float wqs = sW[kk * 64 + col];
            float wks = sW[4096 + kk * 64 + col];
            float wvs = sW[8192 + kk * 64 + col];
            u64 wq2 = pk2(wqs, wqs);
            u64 wk2 = pk2(wks, wks);
            u64 wv2 = pk2(wvs, wvs);
            const u64* xp = (const u64*)&sxT[kk * 34 + r0t];
            #pragma unroll
            for (int j = 0; j < 4; j++) {
                u64 xj = xp[j];
                fma2(aq[j], xj, wq2);
                fma2(ak[j], xj, wk2);
                fma2(av[j], xj, wv2);
            }
        }
        #pragma unroll
        for (int j = 0; j < 4; j++) {
            float q0, q1, k0, k1, v0, v1;
            unpk2(aq[j], q0, q1);
            unpk2(ak[j], k0, k1);
            unpk2(av[j], v0, v1);
            int row = row0 + r0t + 2 * j;
            if (row < N_NODES) {
                g_qh[row * 64 + pcol] = __float2half(q0 + bqv);
                g_kh[row * 64 + pcol] = __float2half(k0 + bkv);
                vout[row * 64 + col]  = v0 + bvv;
            }
            if (row + 1 < N_NODES) {
                g_qh[(row + 1) * 64 + pcol] = __float2half(q1 + bqv);
                g_kh[(row + 1) * 64 + pcol] = __float2half(k1 + bkv);
                vout[(row + 1) * 64 + col]  = v1 + bvv;
            }
        }
    }
}

// Fused: prods + exp + segment-sum. Thread = (edge, d). fp16 q/k layout makes
// each gather one 16B vector load per operand. Dot accumulated in fp32.
__global__ void prods_exp_kernel(const int* __restrict__ edge,
                                 float* __restrict__ prods_out) {
    int idx = blockIdx.x * blockDim.x + threadIdx.x;
    if (idx >= N_EDGES * 8) return;
    int e = idx >> 3;
    int d = idx & 7;
    int s = __ldg(&edge[e]);
    int t = __ldg(&edge[N_EDGES + e]);
    uint4 qv = *(const uint4*)(g_qh + s * 64 + d * 8);
    uint4 kv = *(const uint4*)(g_kh + t * 64 + d * 8);
    const __half2* qh = (const __half2*)&qv;
    const __half2* kh = (const __half2*)&kv;
    float acc = 0.0f;
    #pragma unroll
    for (int i = 0; i < 4; i++) {
        float2 qf = __half22float2(qh[i]);
        float2 kf = __half22float2(kh[i]);
        acc += qf.x * kf.x + qf.y * kf.y;
    }
    float p = acc * 0.35355339059327373f;  // 1/sqrt(8)
    prods_out[idx] = p;
    float ex = __expf(p);  // no max subtraction: p ~ N(0,1), cannot overflow
    atomicAdd(&g_segsum[t * 8 + d], ex);
}

// One edge per thread: att = exp(prods) / (segsum + 1e-16), vectorized.
__global__ void norm_kernel(const int* __restrict__ edge,
                            const float* __restrict__ prods,
                            float* __restrict__ att) {
    int e = blockIdx.x * blockDim.x + threadIdx.x;
    if (e >= N_EDGES) return;
    int t = __ldg(&edge[N_EDGES + e]);
    const float4* sp = (const float4*)&g_segsum[t * 8];
    float4 s0 = sp[0], s1 = sp[1];
    const float4* pp = (const float4*)&prods[(size_t)e * 8];
    float4 p0 = pp[0], p1 = pp[1];
    float4 a0, a1;
    a0.x = __fdividef(__expf(p0.x), s0.x + 1e-16f);
    a0.y = __fdividef(__expf(p0.y), s0.y + 1e-16f);
    a0.z = __fdividef(__expf(p0.z), s0.z + 1e-16f);
    a0.w = __fdividef(__expf(p0.w), s0.w + 1e-16f);
    a1.x = __fdividef(__expf(p1.x), s1.x + 1e-16f);
    a1.y = __fdividef(__expf(p1.y), s1.y + 1e-16f);
    a1.z = __fdividef(__expf(p1.z), s1.z + 1e-16f);
    a1.w = __fdividef(__expf(p1.w), s1.w + 1e-16f);
    float4* ap = (float4*)&att[(size_t)e * 8];
    ap[0] = a0;
    ap[1] = a1;
}

extern "C" void kernel_launch(void* const* d_in, const int* in_sizes, int n_in,
                              void* d_out, int out_size) {
    const float* x    = (const float*)d_in[0];
    const float* Wq   = (const float*)d_in[1];
    const float* bq   = (const float*)d_in[2];
    const float* Wk   = (const float*)d_in[3];
    const float* bk   = (const float*)d_in[4];
    const float* Wv   = (const float*)d_in[5];
    const float* bv   = (const float*)d_in[6];
    const int*   edge = (const int*)d_in[7];

    float* out   = (float*)d_out;
    float* att   = out;                                               // [E*8]
    float* vout  = out + (size_t)N_EDGES * 8;                         // [N*64]
    float* prods = out + (size_t)N_EDGES * 8 + (size_t)N_NODES * 64;  // [E*8]

    const int QKV_SMEM = (12288 + 64 * 34) * 4;  // 57856 bytes
    static void* segsum_ptr = nullptr;
    if (!segsum_ptr) {
        cudaFuncSetAttribute(qkv_kernel, cudaFuncAttributeMaxDynamicSharedMemorySize, QKV_SMEM);
        cudaGetSymbolAddress(&segsum_ptr, g_segsum);
    }

    // Zero segment sums via async memset (graph-capturable node)
    cudaMemsetAsync(segsum_ptr, 0, N_NODES * 8 * sizeof(float), 0);

    qkv_kernel<<<444, 256, QKV_SMEM>>>(x, Wq, bq, Wk, bk, Wv, bv, vout);

    int n_ed = N_EDGES * 8;
    prods_exp_kernel<<<(n_ed + 255) / 256, 256>>>(edge, prods);
    norm_kernel<<<(N_EDGES + 255) / 256, 256>>>(edge, prods, att);
}

// round 10
// speedup vs baseline: 1.6439x; 1.4513x over previous
#include <cuda_runtime.h>
#include <cuda_fp16.h>

#define N_NODES 50000
#define N_EDGES 800000

// Scratch. q,k stored as fp16 in transposed-row layout: g_qh[node*64 + d*8 + h]
// so the 8 threads of one edge gather a full coalesced 128B line per node.
__device__ __half g_qh[N_NODES * 64];
__device__ __half g_kh[N_NODES * 64];
__device__ float  g_segsum[N_NODES * 8];

typedef unsigned long long u64;

__device__ __forceinline__ u64 pk2(float a, float b) {
    u64 r; asm("mov.b64 %0, {%1, %2};" : "=l"(r) : "f"(a), "f"(b)); return r;
}
__device__ __forceinline__ void fma2(u64 &d, u64 a, u64 b) {
    asm("fma.rn.f32x2 %0, %1, %2, %0;" : "+l"(d) : "l"(a), "l"(b));
}
__device__ __forceinline__ void unpk2(u64 a, float &x, float &y) {
    asm("mov.b64 {%0, %1}, %2;" : "=f"(x), "=f"(y) : "l"(a));
}

// Fused QKV projection, occupancy-tuned. Dynamic smem = 41472 B:
//   [0)      sW[2][4096]   Wq, Wk
//   [8192)   sxT[64][34]   x tile transposed (stride 34 keeps LDS.64 aligned)
// Wv is read via uniform __ldg (16KB, L1-resident; one coalesced 128B
// warp-load per kk). 5 CTAs/SM -> 40 warps (vs 24 before).
// Tile: 32 rows. Thread (g,col): rows 8g..8g+7 as 4 row-pairs, column col.
// q,k written fp16 with in-row transpose perm: out column = (col%8)*8 + col/8.
extern __shared__ float dsm[];
__global__ void __launch_bounds__(256, 5)
qkv_kernel(const float* __restrict__ x,
           const float* __restrict__ Wq, const float* __restrict__ bq,
           const float* __restrict__ Wk, const float* __restrict__ bk,
           const float* __restrict__ Wv, const float* __restrict__ bv,
           float* __restrict__ vout) {
    float* sW  = dsm;            // 2*4096
    float* sxT = dsm + 8192;     // 64*34

    int tid = threadIdx.x;
    for (int i = tid; i < 4096; i += 256) {
        sW[i]        = Wq[i];
        sW[4096 + i] = Wk[i];
    }

    int col = tid & 63;
    int g   = tid >> 6;      // 0..3
    int r0t = g * 8;         // local row base
    int pcol = (col & 7) * 8 + (col >> 3);  // transposed column for q,k

    // biases in registers (uniform per column)
    float bqv = __ldg(&bq[col]);
    float bkv = __ldg(&bk[col]);
    float bvv = __ldg(&bv[col]);

    const int n_tiles = (N_NODES + 31) / 32;  // 1563
    for (int tile = blockIdx.x; tile < n_tiles; tile += gridDim.x) {
        int row0 = tile * 32;
        __syncthreads();
        for (int i = tid; i < 32 * 64; i += 256) {
            int r = i >> 6, c = i & 63;
            sxT[c * 34 + r] = (row0 + r < N_NODES) ? x[(row0 + r) * 64 + c] : 0.0f;
        }
        __syncthreads();

        u64 aq[4] = {0,0,0,0}, ak[4] = {0,0,0,0}, av[4] = {0,0,0,0};
        #pragma unroll 8
        for (int kk = 0; kk < 64; kk++) {
            float wqs = sW[kk * 64 + col];
            float wks = sW[4096 + kk * 64 + col];
            float wvs = __ldg(&Wv[kk * 64 + col]);
            u64 wq2 = pk2(wqs, wqs);
            u64 wk2 = pk2(wks, wks);
            u64 wv2 = pk2(wvs, wvs);
            const u64* xp = (const u64*)&sxT[kk * 34 + r0t];
            #pragma unroll
            for (int j = 0; j < 4; j++) {
                u64 xj = xp[j];
                fma2(aq[j], xj, wq2);
                fma2(ak[j], xj, wk2);
                fma2(av[j], xj, wv2);
            }
        }
        #pragma unroll
        for (int j = 0; j < 4; j++) {
            float q0, q1, k0, k1, v0, v1;
            unpk2(aq[j], q0, q1);
            unpk2(ak[j], k0, k1);
            unpk2(av[j], v0, v1);
            int row = row0 + r0t + 2 * j;
            if (row < N_NODES) {
                g_qh[row * 64 + pcol] = __float2half(q0 + bqv);
                g_kh[row * 64 + pcol] = __float2half(k0 + bkv);
                vout[row * 64 + col]  = v0 + bvv;
            }
            if (row + 1 < N_NODES) {
                g_qh[(row + 1) * 64 + pcol] = __float2half(q1 + bqv);
                g_kh[(row + 1) * 64 + pcol] = __float2half(k1 + bkv);
                vout[(row + 1) * 64 + col]  = v1 + bvv;
            }
        }
    }
}

// Fused: prods + exp + segment-sum. Thread = (edge, d). fp16 q/k: the 8
// threads of one edge read one full 128B line per node (fully coalesced).
__global__ void prods_exp_kernel(const int* __restrict__ edge,
                                 float* __restrict__ prods_out) {
    int idx = blockIdx.x * blockDim.x + threadIdx.x;
    if (idx >= N_EDGES * 8) return;
    int e = idx >> 3;
    int d = idx & 7;
    int s = __ldg(&edge[e]);
    int t = __ldg(&edge[N_EDGES + e]);
    uint4 qv = *(const uint4*)(g_qh + s * 64 + d * 8);
    uint4 kv = *(const uint4*)(g_kh + t * 64 + d * 8);
    const __half2* qh = (const __half2*)&qv;
    const __half2* kh = (const __half2*)&kv;
    float acc = 0.0f;
    #pragma unroll
    for (int i = 0; i < 4; i++) {
        float2 qf = __half22float2(qh[i]);
        float2 kf = __half22float2(kh[i]);
        acc += qf.x * kf.x + qf.y * kf.y;
    }
    float p = acc * 0.35355339059327373f;  // 1/sqrt(8)
    prods_out[idx] = p;
    float ex = __expf(p);  // no max subtraction: p ~ N(0,1), cannot overflow
    atomicAdd(&g_segsum[t * 8 + d], ex);
}

// One edge per thread: att = exp(prods) / (segsum + 1e-16), vectorized.
__global__ void norm_kernel(const int* __restrict__ edge,
                            const float* __restrict__ prods,
                            float* __restrict__ att) {
    int e = blockIdx.x * blockDim.x + threadIdx.x;
    if (e >= N_EDGES) return;
    int t = __ldg(&edge[N_EDGES + e]);
    const float4* sp = (const float4*)&g_segsum[t * 8];
    float4 s0 = sp[0], s1 = sp[1];
    const float4* pp = (const float4*)&prods[(size_t)e * 8];
    float4 p0 = pp[0], p1 = pp[1];
    float4 a0, a1;
    a0.x = __fdividef(__expf(p0.x), s0.x + 1e-16f);
    a0.y = __fdividef(__expf(p0.y), s0.y + 1e-16f);
    a0.z = __fdividef(__expf(p0.z), s0.z + 1e-16f);
    a0.w = __fdividef(__expf(p0.w), s0.w + 1e-16f);
    a1.x = __fdividef(__expf(p1.x), s1.x + 1e-16f);
    a1.y = __fdividef(__expf(p1.y), s1.y + 1e-16f);
    a1.z = __fdividef(__expf(p1.z), s1.z + 1e-16f);
    a1.w = __fdividef(__expf(p1.w), s1.w + 1e-16f);
    float4* ap = (float4*)&att[(size_t)e * 8];
    ap[0] = a0;
    ap[1] = a1;
}

extern "C" void kernel_launch(void* const* d_in, const int* in_sizes, int n_in,
                              void* d_out, int out_size) {
    const float* x    = (const float*)d_in[0];
    const float* Wq   = (const float*)d_in[1];
    const float* bq   = (const float*)d_in[2];
    const float* Wk   = (const float*)d_in[3];
    const float* bk   = (const float*)d_in[4];
    const float* Wv   = (const float*)d_in[5];
    const float* bv   = (const float*)d_in[6];
    const int*   edge = (const int*)d_in[7];

    float* out   = (float*)d_out;
    float* att   = out;                                               // [E*8]
    float* vout  = out + (size_t)N_EDGES * 8;                         // [N*64]
    float* prods = out + (size_t)N_EDGES * 8 + (size_t)N_NODES * 64;  // [E*8]

    const int QKV_SMEM = (8192 + 64 * 34) * 4;  // 41472 bytes -> 5 CTAs/SM
    static void* segsum_ptr = nullptr;
    if (!segsum_ptr) {
        cudaFuncSetAttribute(qkv_kernel, cudaFuncAttributeMaxDynamicSharedMemorySize, QKV_SMEM);
        cudaGetSymbolAddress(&segsum_ptr, g_segsum);
    }

    // Zero segment sums via async memset (graph-capturable node)
    cudaMemsetAsync(segsum_ptr, 0, N_NODES * 8 * sizeof(float), 0);

    // 5 CTAs/SM * 148 SMs = one balanced wave over 1563 tiles
    qkv_kernel<<<740, 256, QKV_SMEM>>>(x, Wq, bq, Wk, bk, Wv, bv, vout);

    int n_ed = N_EDGES * 8;
    prods_exp_kernel<<<(n_ed + 255) / 256, 256>>>(edge, prods);
    norm_kernel<<<(N_EDGES + 255) / 256, 256>>>(edge, prods, att);
}